// round 9
// baseline (speedup 1.0000x reference)
#include <cuda_runtime.h>

// SSIM loss — R9: R8 + 16B-aligned V-buffers (stride 78), LDS.128 phase-2
// window loads (half the LDS wavefronts), front-loaded MLP across both fields.

typedef unsigned long long u64;

#define TX 64
#define TY 32
#define HALO 5
#define INW 74                      // TX + 2*HALO
#define VS 78                       // u64 stride: even (16B rows), quad-stride 39 = 7 mod 8
#define NTHREADS 256
#define IMG 512
#define TILES_X 8
#define TILES_Y 16
#define PLANES 48
#define NBLOCKS (PLANES * TILES_Y * TILES_X)   // 6144
#define NPIX 12582912.0f

#define C1 1.0e-4f
#define C2 9.0e-4f

#define N_V (TY * VS)               // 2496 u64 per buffer

__device__ float g_partials[NBLOCKS];
__device__ unsigned g_ticket = 0;

// Normalized 1D Gaussian, window=11, sigma=1.5
__device__ __forceinline__ constexpr float Wt(int k) {
    constexpr float w[11] = {
        0.00102838f, 0.00759877f, 0.03600081f, 0.10936072f, 0.21300553f,
        0.26601169f,
        0.21300553f, 0.10936072f, 0.03600081f, 0.00759877f, 0.00102838f
    };
    return w[k];
}

// ---- f32x2 packed helpers ----
__device__ __forceinline__ u64 pk(float lo, float hi) {
    u64 r; asm("mov.b64 %0, {%1, %2};" : "=l"(r) : "f"(lo), "f"(hi)); return r;
}
__device__ __forceinline__ float2 upk(u64 v) {
    float2 r; asm("mov.b64 {%0, %1}, %2;" : "=f"(r.x), "=f"(r.y) : "l"(v)); return r;
}
__device__ __forceinline__ u64 fma2(u64 a, u64 b, u64 c) {
    u64 d; asm("fma.rn.f32x2 %0, %1, %2, %3;" : "=l"(d) : "l"(a), "l"(b), "l"(c)); return d;
}
__device__ __forceinline__ u64 mul2(u64 a, u64 b) {
    u64 d; asm("mul.rn.f32x2 %0, %1, %2;" : "=l"(d) : "l"(a), "l"(b)); return d;
}
__device__ __forceinline__ u64 wsel(const u64 (&w)[6], int k) {
    return w[k < 6 ? k : 10 - k];
}

// Vertical-blur task: WIN input rows -> NOUT output rows for column c.
template<int WIN, int NOUT>
__device__ __forceinline__ void vtask(
    const float* __restrict__ p_plane, const float* __restrict__ t_plane,
    bool interior, int gx, int gybase,
    u64* __restrict__ s_VA, u64* __restrict__ s_VB,
    int y0, int c, const u64 (&w2)[6])
{
    u64 a[WIN];
    if (interior) {
        const float* pp = p_plane + (long)gybase * IMG + gx;
        const float* tp = t_plane + (long)gybase * IMG + gx;
        #pragma unroll
        for (int i = 0; i < WIN; i++)
            a[i] = pk(__ldg(pp + i * IMG), __ldg(tp + i * IMG));
    } else {
        const bool xok = (unsigned)gx < IMG;
        #pragma unroll
        for (int i = 0; i < WIN; i++) {
            int gy = gybase + i;
            float pv = 0.0f, tv = 0.0f;
            if (xok & ((unsigned)gy < IMG)) {
                long o = (long)gy * IMG + gx;
                pv = __ldg(p_plane + o);
                tv = __ldg(t_plane + o);
            }
            a[i] = pk(pv, tv);
        }
    }
    #pragma unroll
    for (int j = 0; j < NOUT; j++) {
        u64 acc = mul2(wsel(w2, 0), a[j]);
        #pragma unroll
        for (int k = 1; k < 11; k++) acc = fma2(wsel(w2, k), a[j + k], acc);
        s_VA[(y0 + j) * VS + c] = acc;
    }
    #pragma unroll
    for (int i = 0; i < WIN; i++) {     // (p,t) -> (p^2+t^2, p*t)
        float2 v = upk(a[i]);
        a[i] = pk(fmaf(v.x, v.x, v.y * v.y), v.x * v.y);
    }
    #pragma unroll
    for (int j = 0; j < NOUT; j++) {
        u64 acc = mul2(wsel(w2, 0), a[j]);
        #pragma unroll
        for (int k = 1; k < 11; k++) acc = fma2(wsel(w2, k), a[j + k], acc);
        s_VB[(y0 + j) * VS + c] = acc;
    }
}

__global__ __launch_bounds__(NTHREADS, 5)
void ssim_tile_kernel(const float* __restrict__ pred,
                      const float* __restrict__ targ,
                      float* __restrict__ out) {
    __shared__ __align__(16) u64 s_VA[N_V];   // V-blurred (mu_p, mu_t)
    __shared__ __align__(16) u64 s_VB[N_V];   // V-blurred (E[p^2]+E[t^2], E[pt])
    __shared__ float s_warp[8];
    __shared__ int   s_last;

    const int tid = threadIdx.x;
    const int ox = blockIdx.x * TX;
    const int oy = blockIdx.y * TY;
    const long plane_base = (long)blockIdx.z * (IMG * IMG);
    const float* __restrict__ p_plane = pred + plane_base;
    const float* __restrict__ t_plane = targ + plane_base;

    u64 w2[6];
    #pragma unroll
    for (int k = 0; k < 6; k++) w2[k] = pk(Wt(k), Wt(k));

    // ---- Phase 1: vertical blur from global.
    // 444 tasks = 74 halo-cols x 6 exact row-groups {6,6,6,6,4,4}.
    const bool interior =
        (blockIdx.x != 0) & (blockIdx.x != TILES_X - 1) &
        (blockIdx.y != 0) & (blockIdx.y != TILES_Y - 1);

    #pragma unroll 1
    for (int it = 0; it < 2; it++) {
        int task = tid + it * NTHREADS;
        if (task < INW * 6) {
            int c = task % INW;
            int g = task / INW;
            int gx = ox + c - HALO;
            if (g < 4) {
                int y0 = 6 * g;
                vtask<16, 6>(p_plane, t_plane, interior, gx,
                             oy + y0 - HALO, s_VA, s_VB, y0, c, w2);
            } else {
                int y0 = 4 * g + 8;          // 24, 28
                vtask<14, 4>(p_plane, t_plane, interior, gx,
                             oy + y0 - HALO, s_VA, s_VB, y0, c, w2);
            }
        }
    }
    __syncthreads();

    // ---- Phase 2: horizontal blur + SSIM. 512 tasks of 4 cols, 2 rounds.
    // Windows loaded via LDS.128 (7 per field), all 14 issued before chains.
    float local = 0.0f;
    #pragma unroll
    for (int it = 0; it < 2; it++) {
        const int task = tid + it * NTHREADS;   // 0..511
        const int r = task & 31;
        const int grp = task >> 5;              // 0..15
        const int base = r * VS + 4 * grp;      // even -> 16B aligned

        const ulonglong2* pa = (const ulonglong2*)(s_VA + base);
        const ulonglong2* pb = (const ulonglong2*)(s_VB + base);
        ulonglong2 va[7], vb[7];
        #pragma unroll
        for (int i = 0; i < 7; i++) va[i] = pa[i];
        #pragma unroll
        for (int i = 0; i < 7; i++) vb[i] = pb[i];

        u64 hA[14], hB[14];
        #pragma unroll
        for (int i = 0; i < 7; i++) {
            hA[2*i] = va[i].x; hA[2*i+1] = va[i].y;
            hB[2*i] = vb[i].x; hB[2*i+1] = vb[i].y;
        }

        u64 amu[4], asb[4];
        #pragma unroll
        for (int j = 0; j < 4; j++) {
            u64 acc = mul2(wsel(w2, 0), hA[j]);
            #pragma unroll
            for (int k = 1; k < 11; k++) acc = fma2(wsel(w2, k), hA[j + k], acc);
            amu[j] = acc;
        }
        #pragma unroll
        for (int j = 0; j < 4; j++) {
            u64 acc = mul2(wsel(w2, 0), hB[j]);
            #pragma unroll
            for (int k = 1; k < 11; k++) acc = fma2(wsel(w2, k), hB[j + k], acc);
            asb[j] = acc;
        }
        #pragma unroll
        for (int j = 0; j < 4; j++) {
            float2 mu = upk(amu[j]);
            float2 sb = upk(asb[j]);        // (E[p^2]+E[t^2], E[pt])
            float mu_p2 = mu.x * mu.x;
            float mu_t2 = mu.y * mu.y;
            float mu_pt = mu.x * mu.y;
            float num = (2.0f * mu_pt + C1) * (2.0f * (sb.y - mu_pt) + C2);
            float den = (mu_p2 + mu_t2 + C1) * ((sb.x - mu_p2 - mu_t2) + C2);
            local += __fdividef(num, den);
        }
    }

    // ---- Phase 3: block reduction ----
    float v = local;
    #pragma unroll
    for (int off = 16; off; off >>= 1)
        v += __shfl_xor_sync(0xFFFFFFFFu, v, off);
    if ((tid & 31) == 0) s_warp[tid >> 5] = v;
    __syncthreads();
    if (tid < 8) {
        v = s_warp[tid];
        #pragma unroll
        for (int off = 4; off; off >>= 1)
            v += __shfl_xor_sync(0x000000FFu, v, off);
    }
    if (tid == 0) {
        int bl = (blockIdx.z * TILES_Y + blockIdx.y) * TILES_X + blockIdx.x;
        g_partials[bl] = v;
        __threadfence();
        unsigned t = atomicInc(&g_ticket, NBLOCKS - 1);  // wraps -> self-reset
        s_last = (t == NBLOCKS - 1);
    }
    __syncthreads();

    // ---- Phase 4: last block folds partials (fixed order, deterministic) ----
    if (s_last) {
        float s = 0.0f;
        for (int i = tid; i < NBLOCKS; i += NTHREADS)
            s += __ldcg(&g_partials[i]);
        #pragma unroll
        for (int off = 16; off; off >>= 1)
            s += __shfl_xor_sync(0xFFFFFFFFu, s, off);
        if ((tid & 31) == 0) s_warp[tid >> 5] = s;
        __syncthreads();
        if (tid < 8) {
            s = s_warp[tid];
            #pragma unroll
            for (int off = 4; off; off >>= 1)
                s += __shfl_xor_sync(0x000000FFu, s, off);
            if (tid == 0) out[0] = 1.0f - s * (1.0f / NPIX);
        }
    }
}

extern "C" void kernel_launch(void* const* d_in, const int* in_sizes, int n_in,
                              void* d_out, int out_size) {
    const float* pred = (const float*)d_in[0];
    const float* targ = (const float*)d_in[1];
    float* out = (float*)d_out;

    dim3 grid(TILES_X, TILES_Y, PLANES);
    ssim_tile_kernel<<<grid, NTHREADS>>>(pred, targ, out);
}

// round 10
// speedup vs baseline: 1.2132x; 1.2132x over previous
#include <cuda_runtime.h>

// SSIM loss — R10: R8 structure (64x32 tiles, two-field algebra, scalar-LDS.64
// phase 2) with phase-1 regrouped to 4x8-output tasks (window 18): row
// redundancy 92->72 per column (-22% LDG + transform work).

typedef unsigned long long u64;

#define TX 64
#define TY 32
#define HALO 5
#define INW 74                      // TX + 2*HALO
#define VS 75                       // V-buffer stride in u64 (odd, gcd(75,16)=1)
#define NTHREADS 256
#define IMG 512
#define TILES_X 8
#define TILES_Y 16
#define PLANES 48
#define NBLOCKS (PLANES * TILES_Y * TILES_X)   // 6144
#define NPIX 12582912.0f

#define C1 1.0e-4f
#define C2 9.0e-4f

#define N_V (TY * VS)               // 2400 u64 per buffer

__device__ float g_partials[NBLOCKS];
__device__ unsigned g_ticket = 0;

// Normalized 1D Gaussian, window=11, sigma=1.5
__device__ __forceinline__ constexpr float Wt(int k) {
    constexpr float w[11] = {
        0.00102838f, 0.00759877f, 0.03600081f, 0.10936072f, 0.21300553f,
        0.26601169f,
        0.21300553f, 0.10936072f, 0.03600081f, 0.00759877f, 0.00102838f
    };
    return w[k];
}

// ---- f32x2 packed helpers ----
__device__ __forceinline__ u64 pk(float lo, float hi) {
    u64 r; asm("mov.b64 %0, {%1, %2};" : "=l"(r) : "f"(lo), "f"(hi)); return r;
}
__device__ __forceinline__ float2 upk(u64 v) {
    float2 r; asm("mov.b64 {%0, %1}, %2;" : "=f"(r.x), "=f"(r.y) : "l"(v)); return r;
}
__device__ __forceinline__ u64 fma2(u64 a, u64 b, u64 c) {
    u64 d; asm("fma.rn.f32x2 %0, %1, %2, %3;" : "=l"(d) : "l"(a), "l"(b), "l"(c)); return d;
}
__device__ __forceinline__ u64 mul2(u64 a, u64 b) {
    u64 d; asm("mul.rn.f32x2 %0, %1, %2;" : "=l"(d) : "l"(a), "l"(b)); return d;
}
__device__ __forceinline__ u64 wsel(const u64 (&w)[6], int k) {
    return w[k < 6 ? k : 10 - k];
}

// Vertical-blur task: WIN input rows -> NOUT output rows for column c.
template<int WIN, int NOUT>
__device__ __forceinline__ void vtask(
    const float* __restrict__ p_plane, const float* __restrict__ t_plane,
    bool interior, int gx, int gybase,
    u64* __restrict__ s_VA, u64* __restrict__ s_VB,
    int y0, int c, const u64 (&w2)[6])
{
    u64 a[WIN];
    if (interior) {
        const float* pp = p_plane + (long)gybase * IMG + gx;
        const float* tp = t_plane + (long)gybase * IMG + gx;
        #pragma unroll
        for (int i = 0; i < WIN; i++)
            a[i] = pk(__ldg(pp + i * IMG), __ldg(tp + i * IMG));
    } else {
        const bool xok = (unsigned)gx < IMG;
        #pragma unroll
        for (int i = 0; i < WIN; i++) {
            int gy = gybase + i;
            float pv = 0.0f, tv = 0.0f;
            if (xok & ((unsigned)gy < IMG)) {
                long o = (long)gy * IMG + gx;
                pv = __ldg(p_plane + o);
                tv = __ldg(t_plane + o);
            }
            a[i] = pk(pv, tv);
        }
    }
    #pragma unroll
    for (int j = 0; j < NOUT; j++) {
        u64 acc = mul2(wsel(w2, 0), a[j]);
        #pragma unroll
        for (int k = 1; k < 11; k++) acc = fma2(wsel(w2, k), a[j + k], acc);
        s_VA[(y0 + j) * VS + c] = acc;
    }
    #pragma unroll
    for (int i = 0; i < WIN; i++) {     // (p,t) -> (p^2+t^2, p*t)
        float2 v = upk(a[i]);
        a[i] = pk(fmaf(v.x, v.x, v.y * v.y), v.x * v.y);
    }
    #pragma unroll
    for (int j = 0; j < NOUT; j++) {
        u64 acc = mul2(wsel(w2, 0), a[j]);
        #pragma unroll
        for (int k = 1; k < 11; k++) acc = fma2(wsel(w2, k), a[j + k], acc);
        s_VB[(y0 + j) * VS + c] = acc;
    }
}

__global__ __launch_bounds__(NTHREADS, 5)
void ssim_tile_kernel(const float* __restrict__ pred,
                      const float* __restrict__ targ,
                      float* __restrict__ out) {
    __shared__ u64 s_VA[N_V];     // V-blurred (mu_p, mu_t)
    __shared__ u64 s_VB[N_V];     // V-blurred (E[p^2]+E[t^2], E[pt])
    __shared__ float s_warp[8];
    __shared__ int   s_last;

    const int tid = threadIdx.x;
    const int ox = blockIdx.x * TX;
    const int oy = blockIdx.y * TY;
    const long plane_base = (long)blockIdx.z * (IMG * IMG);
    const float* __restrict__ p_plane = pred + plane_base;
    const float* __restrict__ t_plane = targ + plane_base;

    u64 w2[6];
    #pragma unroll
    for (int k = 0; k < 6; k++) w2[k] = pk(Wt(k), Wt(k));

    // ---- Phase 1: vertical blur from global.
    // 296 tasks = 74 halo-cols x 4 row-groups of 8 outputs (window 18).
    const bool interior =
        (blockIdx.x != 0) & (blockIdx.x != TILES_X - 1) &
        (blockIdx.y != 0) & (blockIdx.y != TILES_Y - 1);

    #pragma unroll 1
    for (int it = 0; it < 2; it++) {
        int task = tid + it * NTHREADS;
        if (task < INW * 4) {
            int c = task % INW;
            int g = task / INW;
            int gx = ox + c - HALO;
            int y0 = 8 * g;
            vtask<18, 8>(p_plane, t_plane, interior, gx,
                         oy + y0 - HALO, s_VA, s_VB, y0, c, w2);
        }
    }
    __syncthreads();

    // ---- Phase 2: horizontal blur + SSIM. 512 tasks of 4 cols, 2 rounds.
    // (R8 form: per-field scalar LDS.64 windows — small live set.)
    float local = 0.0f;
    #pragma unroll
    for (int it = 0; it < 2; it++) {
        const int task = tid + it * NTHREADS;   // 0..511
        const int r = task & 31;
        const int grp = task >> 5;              // 0..15
        const int base = r * VS + 4 * grp;

        u64 amu[4];
        {
            u64 h[14];
            #pragma unroll
            for (int i = 0; i < 14; i++) h[i] = s_VA[base + i];
            #pragma unroll
            for (int j = 0; j < 4; j++) {
                u64 acc = mul2(wsel(w2, 0), h[j]);
                #pragma unroll
                for (int k = 1; k < 11; k++) acc = fma2(wsel(w2, k), h[j + k], acc);
                amu[j] = acc;
            }
        }
        u64 asb[4];
        {
            u64 h[14];
            #pragma unroll
            for (int i = 0; i < 14; i++) h[i] = s_VB[base + i];
            #pragma unroll
            for (int j = 0; j < 4; j++) {
                u64 acc = mul2(wsel(w2, 0), h[j]);
                #pragma unroll
                for (int k = 1; k < 11; k++) acc = fma2(wsel(w2, k), h[j + k], acc);
                asb[j] = acc;
            }
        }
        #pragma unroll
        for (int j = 0; j < 4; j++) {
            float2 mu = upk(amu[j]);
            float2 sb = upk(asb[j]);        // (E[p^2]+E[t^2], E[pt])
            float mu_p2 = mu.x * mu.x;
            float mu_t2 = mu.y * mu.y;
            float mu_pt = mu.x * mu.y;
            float num = (2.0f * mu_pt + C1) * (2.0f * (sb.y - mu_pt) + C2);
            float den = (mu_p2 + mu_t2 + C1) * ((sb.x - mu_p2 - mu_t2) + C2);
            local += __fdividef(num, den);
        }
    }

    // ---- Phase 3: block reduction ----
    float v = local;
    #pragma unroll
    for (int off = 16; off; off >>= 1)
        v += __shfl_xor_sync(0xFFFFFFFFu, v, off);
    if ((tid & 31) == 0) s_warp[tid >> 5] = v;
    __syncthreads();
    if (tid < 8) {
        v = s_warp[tid];
        #pragma unroll
        for (int off = 4; off; off >>= 1)
            v += __shfl_xor_sync(0x000000FFu, v, off);
    }
    if (tid == 0) {
        int bl = (blockIdx.z * TILES_Y + blockIdx.y) * TILES_X + blockIdx.x;
        g_partials[bl] = v;
        __threadfence();
        unsigned t = atomicInc(&g_ticket, NBLOCKS - 1);  // wraps -> self-reset
        s_last = (t == NBLOCKS - 1);
    }
    __syncthreads();

    // ---- Phase 4: last block folds partials (fixed order, deterministic) ----
    if (s_last) {
        float s = 0.0f;
        for (int i = tid; i < NBLOCKS; i += NTHREADS)
            s += __ldcg(&g_partials[i]);
        #pragma unroll
        for (int off = 16; off; off >>= 1)
            s += __shfl_xor_sync(0xFFFFFFFFu, s, off);
        if ((tid & 31) == 0) s_warp[tid >> 5] = s;
        __syncthreads();
        if (tid < 8) {
            s = s_warp[tid];
            #pragma unroll
            for (int off = 4; off; off >>= 1)
                s += __shfl_xor_sync(0x000000FFu, s, off);
            if (tid == 0) out[0] = 1.0f - s * (1.0f / NPIX);
        }
    }
}

extern "C" void kernel_launch(void* const* d_in, const int* in_sizes, int n_in,
                              void* d_out, int out_size) {
    const float* pred = (const float*)d_in[0];
    const float* targ = (const float*)d_in[1];
    float* out = (float*)d_out;

    dim3 grid(TILES_X, TILES_Y, PLANES);
    ssim_tile_kernel<<<grid, NTHREADS>>>(pred, targ, out);
}